// round 13
// baseline (speedup 1.0000x reference)
#include <cuda_runtime.h>
#include <cuda_bf16.h>

// SelfAttention: B=32, D=2048
// q = x@Wq^T+bq ; k,v similarly
// scores[b,i,j] = q_i*k_j ; softmax over i ; out_i = sum_j w_ij * v_j
//
// Rank-1 truncated formulation:
//   arg_ij = k2_j*(q_i - qsel_j) <= 0, k2 = k*log2(e), qsel = (k>0 ? qmax : qmin)
//   Terms with arg < -TCUT (=28) contribute < 2^-28 of the column max -> dropped.
//   prep:  sort q ascending (values+idx); sort j by (sign k2, |k2| asc);
//          store permuted k2/v arrays.  Deterministic bitonic sorts (no atomics).
//   pass1: thread owns slot s (k2 sorted); contributing i's are a contiguous
//          range of sorted q found by binary search; S_j via MUFU exp;
//          c_s = v_s/S stored in slot order.
//   pass2: thread owns q-sorted position; contributing j's are prefixes of the
//          neg-group (|k2| asc) and pos-group (k2 asc); out_i = sum c*exp.

#define BB 32
#define DD 2048
#define LOG2E 1.4426950408889634f
#define TCUT 28.0f
#define KSPLIT 4
#define KCHUNK 512

typedef unsigned long long ull;

__device__ float g_q[BB * DD];
__device__ float g_k[BB * DD];
__device__ float g_v[BB * DD];
__device__ float g_part[KSPLIT][3 * BB * DD];

__device__ float g_qmax[BB];
__device__ float g_qmin[BB];
__device__ float g_qsrt[BB * DD];   // q values sorted ascending
__device__ int   g_qidx[BB * DD];   // original i per sorted position
__device__ float g_k2s[BB * DD];    // k2 in slot order: negs (|k2| asc) then pos (k2 asc)
__device__ float g_vs[BB * DD];     // v permuted to slot order
__device__ float g_cp[BB * DD];     // c = v/S in slot order (pass1 output)
__device__ int   g_nneg[BB];

__device__ __forceinline__ float ex2f(float x) {
    float r;
    asm("ex2.approx.ftz.f32 %0, %1;" : "=f"(r) : "f"(x));
    return r;
}

// ---------------------------------------------------------------------------
// Kernel A: q/k/v GEMM partials. (unchanged from best)
// ---------------------------------------------------------------------------
__global__ void __launch_bounds__(128) qkv_gemm_part(
    const float* __restrict__ x,
    const float* __restrict__ Wq,
    const float* __restrict__ Wk,
    const float* __restrict__ Wv)
{
    const int bx  = blockIdx.x;
    const int ks  = bx / 96;
    const int r   = bx % 96;
    const int mat = r >> 5;
    const int nt  = r & 31;
    const int n0  = nt * 64;
    const int k0  = ks * KCHUNK;

    const float* W = (mat == 0) ? Wq : (mat == 1) ? Wk : Wv;

    __shared__ float xs[2][32][36];
    __shared__ float ws[2][32][68];

    const int tid = threadIdx.x;
    const int tn  = tid & 15;
    const int tm  = tid >> 4;

    const int xm  = tid >> 2;
    const int xk4 = (tid & 3) * 4;
    const int wn  = tid >> 3;
    const int wk4 = (tid & 7) * 4;

    float acc[4][4];
#pragma unroll
    for (int a = 0; a < 4; a++)
#pragma unroll
        for (int c = 0; c < 4; c++) acc[a][c] = 0.f;

    float4 xr[2], wr[4];

#pragma unroll
    for (int l = 0; l < 2; l++)
        xr[l] = *reinterpret_cast<const float4*>(&x[xm * DD + k0 + xk4 + 16 * l]);
#pragma unroll
    for (int l = 0; l < 4; l++)
        wr[l] = *reinterpret_cast<const float4*>(&W[(n0 + wn + 16 * l) * DD + k0 + wk4]);
#pragma unroll
    for (int l = 0; l < 2; l++) {
        const int kk = xk4 + 16 * l;
        xs[0][kk + 0][xm] = xr[l].x;
        xs[0][kk + 1][xm] = xr[l].y;
        xs[0][kk + 2][xm] = xr[l].z;
        xs[0][kk + 3][xm] = xr[l].w;
    }
#pragma unroll
    for (int l = 0; l < 4; l++) {
        const int n = wn + 16 * l;
        ws[0][wk4 + 0][n] = wr[l].x;
        ws[0][wk4 + 1][n] = wr[l].y;
        ws[0][wk4 + 2][n] = wr[l].z;
        ws[0][wk4 + 3][n] = wr[l].w;
    }

    const int NSTAGE = KCHUNK / 32;
    for (int kt = 0; kt < NSTAGE; kt++) {
        const int p = kt & 1;
        __syncthreads();

        if (kt < NSTAGE - 1) {
            const int kb = k0 + (kt + 1) * 32;
#pragma unroll
            for (int l = 0; l < 2; l++)
                xr[l] = *reinterpret_cast<const float4*>(&x[xm * DD + kb + xk4 + 16 * l]);
#pragma unroll
            for (int l = 0; l < 4; l++)
                wr[l] = *reinterpret_cast<const float4*>(&W[(n0 + wn + 16 * l) * DD + kb + wk4]);
        }

#pragma unroll
        for (int kk = 0; kk < 32; kk++) {
            const float4 xv = *reinterpret_cast<const float4*>(&xs[p][kk][tm * 4]);
            const float4 wv = *reinterpret_cast<const float4*>(&ws[p][kk][tn * 4]);
            acc[0][0] = fmaf(xv.x, wv.x, acc[0][0]);
            acc[0][1] = fmaf(xv.x, wv.y, acc[0][1]);
            acc[0][2] = fmaf(xv.x, wv.z, acc[0][2]);
            acc[0][3] = fmaf(xv.x, wv.w, acc[0][3]);
            acc[1][0] = fmaf(xv.y, wv.x, acc[1][0]);
            acc[1][1] = fmaf(xv.y, wv.y, acc[1][1]);
            acc[1][2] = fmaf(xv.y, wv.z, acc[1][2]);
            acc[1][3] = fmaf(xv.y, wv.w, acc[1][3]);
            acc[2][0] = fmaf(xv.z, wv.x, acc[2][0]);
            acc[2][1] = fmaf(xv.z, wv.y, acc[2][1]);
            acc[2][2] = fmaf(xv.z, wv.z, acc[2][2]);
            acc[2][3] = fmaf(xv.z, wv.w, acc[2][3]);
            acc[3][0] = fmaf(xv.w, wv.x, acc[3][0]);
            acc[3][1] = fmaf(xv.w, wv.y, acc[3][1]);
            acc[3][2] = fmaf(xv.w, wv.z, acc[3][2]);
            acc[3][3] = fmaf(xv.w, wv.w, acc[3][3]);
        }

        if (kt < NSTAGE - 1) {
            const int np = p ^ 1;
#pragma unroll
            for (int l = 0; l < 2; l++) {
                const int kk = xk4 + 16 * l;
                xs[np][kk + 0][xm] = xr[l].x;
                xs[np][kk + 1][xm] = xr[l].y;
                xs[np][kk + 2][xm] = xr[l].z;
                xs[np][kk + 3][xm] = xr[l].w;
            }
#pragma unroll
            for (int l = 0; l < 4; l++) {
                const int n = wn + 16 * l;
                ws[np][wk4 + 0][n] = wr[l].x;
                ws[np][wk4 + 1][n] = wr[l].y;
                ws[np][wk4 + 2][n] = wr[l].z;
                ws[np][wk4 + 3][n] = wr[l].w;
            }
        }
    }

    float* dst = g_part[ks];
#pragma unroll
    for (int a = 0; a < 4; a++) {
        const int m = tm * 4 + a;
        float4 v = make_float4(acc[a][0], acc[a][1], acc[a][2], acc[a][3]);
        *reinterpret_cast<float4*>(&dst[(mat * BB + m) * DD + n0 + tn * 4]) = v;
    }
}

// ---------------------------------------------------------------------------
// Kernel A2: combine k-split partials + bias -> g_q/g_k/g_v. (unchanged)
// ---------------------------------------------------------------------------
__global__ void __launch_bounds__(512) qkv_combine(
    const float* __restrict__ bq,
    const float* __restrict__ bk,
    const float* __restrict__ bv)
{
    const int idx4 = blockIdx.x * 512 + threadIdx.x;
    const float4 p0 = reinterpret_cast<const float4*>(g_part[0])[idx4];
    const float4 p1 = reinterpret_cast<const float4*>(g_part[1])[idx4];
    const float4 p2 = reinterpret_cast<const float4*>(g_part[2])[idx4];
    const float4 p3 = reinterpret_cast<const float4*>(g_part[3])[idx4];

    const int mat  = idx4 / (BB * DD / 4);
    const int rem  = idx4 % (BB * DD / 4);
    const int col4 = idx4 % (DD / 4);

    const float* bias = (mat == 0) ? bq : (mat == 1) ? bk : bv;
    const float4 b4 = reinterpret_cast<const float4*>(bias)[col4];

    float4 o;
    o.x = (p0.x + p1.x) + (p2.x + p3.x) + b4.x;
    o.y = (p0.y + p1.y) + (p2.y + p3.y) + b4.y;
    o.z = (p0.z + p1.z) + (p2.z + p3.z) + b4.z;
    o.w = (p0.w + p1.w) + (p2.w + p3.w) + b4.w;

    float* dst = (mat == 0) ? g_q : (mat == 1) ? g_k : g_v;
    reinterpret_cast<float4*>(dst)[rem] = o;
}

// ---------------------------------------------------------------------------
// Bitonic sort of 2048 ull keys in smem. 1024 threads, 2 elems each.
// Deterministic (keys carry distinct payload in low 32 bits -> total order).
// ---------------------------------------------------------------------------
__device__ __forceinline__ void bitonic2048(ull* a, int tid)
{
    for (int k = 2; k <= 2048; k <<= 1) {
        for (int j = k >> 1; j > 0; j >>= 1) {
            __syncthreads();
#pragma unroll 1
            for (int e = tid; e < 2048; e += 1024) {
                int x = e ^ j;
                if (x > e) {
                    ull u = a[e], w = a[x];
                    bool asc = ((e & k) == 0);
                    if ((u > w) == asc) { a[e] = w; a[x] = u; }
                }
            }
        }
    }
    __syncthreads();
}

// map float -> order-preserving uint
__device__ __forceinline__ unsigned int f2ord(float f) {
    unsigned int u = __float_as_uint(f);
    return (u & 0x80000000u) ? ~u : (u | 0x80000000u);
}
__device__ __forceinline__ float ord2f(unsigned int ou) {
    unsigned int u = (ou & 0x80000000u) ? (ou & 0x7FFFFFFFu) : ~ou;
    return __uint_as_float(u);
}

// ---------------------------------------------------------------------------
// Kernel P: prep. grid = 32 (one CTA per batch row), 1024 threads.
//   - qmax/qmin of q row
//   - sort q ascending -> g_qsrt, g_qidx
//   - sort j by (sign k2 : negs first by |k2| asc, then pos by k2 asc)
//     -> g_k2s, g_vs, g_nneg
// ---------------------------------------------------------------------------
__global__ void __launch_bounds__(1024) prep()
{
    const int b   = blockIdx.x;
    const int tid = threadIdx.x;

    __shared__ ull   arr[DD];          // 16 KB
    __shared__ float red1[32], red2[32];

    const float* qrow = g_q + b * DD;
    const float* krow = g_k + b * DD;
    const float* vrow = g_v + b * DD;

    // ---- qmax / qmin ----
    float q0 = qrow[tid];
    float q1 = qrow[tid + 1024];
    float lmax = fmaxf(q0, q1);
    float lmin = fminf(q0, q1);
#pragma unroll
    for (int o = 16; o; o >>= 1) {
        lmax = fmaxf(lmax, __shfl_xor_sync(0xffffffffu, lmax, o));
        lmin = fminf(lmin, __shfl_xor_sync(0xffffffffu, lmin, o));
    }
    if ((tid & 31) == 0) { red1[tid >> 5] = lmax; red2[tid >> 5] = lmin; }
    __syncthreads();
    if (tid < 32) {
        lmax = red1[tid];
        lmin = red2[tid];
#pragma unroll
        for (int o = 16; o; o >>= 1) {
            lmax = fmaxf(lmax, __shfl_xor_sync(0xffffffffu, lmax, o));
            lmin = fminf(lmin, __shfl_xor_sync(0xffffffffu, lmin, o));
        }
        if (tid == 0) { g_qmax[b] = lmax; g_qmin[b] = lmin; }
    }

    // ---- sort q (value ascending), payload = original index ----
    arr[tid]        = ((ull)f2ord(q0) << 32) | (unsigned int)tid;
    arr[tid + 1024] = ((ull)f2ord(q1) << 32) | (unsigned int)(tid + 1024);
    bitonic2048(arr, tid);
#pragma unroll
    for (int t = tid; t < DD; t += 1024) {
        ull v = arr[t];
        g_qsrt[b * DD + t] = ord2f((unsigned int)(v >> 32));
        g_qidx[b * DD + t] = (int)(v & 0xFFFFFFFFu);
    }
    __syncthreads();

    // ---- sort j by (negs first, |k2| asc ; then pos, k2 asc) ----
#pragma unroll
    for (int t = tid; t < DD; t += 1024) {
        float k2 = LOG2E * krow[t];
        float keyf = (k2 >= 0.f) ? (k2 + 1.0e6f) : (-k2);   // all keys > 0
        arr[t] = ((ull)__float_as_uint(keyf) << 32) | (unsigned int)t;
    }
    bitonic2048(arr, tid);

    int negcnt = 0;
#pragma unroll
    for (int t = tid; t < DD; t += 1024) {
        int j = (int)(arr[t] & 0xFFFFFFFFu);
        float k2 = LOG2E * krow[j];
        g_k2s[b * DD + t] = k2;
        g_vs[b * DD + t]  = vrow[j];
        negcnt += (k2 < 0.f) ? 1 : 0;
    }
    // reduce negcnt
#pragma unroll
    for (int o = 16; o; o >>= 1)
        negcnt += __shfl_xor_sync(0xffffffffu, negcnt, o);
    if ((tid & 31) == 0) red1[tid >> 5] = (float)negcnt;
    __syncthreads();
    if (tid < 32) {
        int c = (int)red1[tid];
#pragma unroll
        for (int o = 16; o; o >>= 1)
            c += __shfl_xor_sync(0xffffffffu, c, o);
        if (tid == 0) g_nneg[b] = c;
    }
}

// slot mapping: global warp w (0..63) + lane -> slot, warp-contiguous,
// CTA-interleaved for load balance across the sorted array.
__device__ __forceinline__ int slot_map(int w, int lane) {
    return ((w & 15) << 7) + ((w >> 4) << 5) + lane;
}

// ---------------------------------------------------------------------------
// Kernel B: pass 1. grid (8, 32), 256 threads. Thread owns one slot s
// (k2-sorted). Sums exp over the contributing contiguous range of sorted q.
// ---------------------------------------------------------------------------
__global__ void __launch_bounds__(256) attn_pass1()
{
    const int b   = blockIdx.y;
    const int bx  = blockIdx.x;
    const int tid = threadIdx.x;

    __shared__ float qs[DD];           // 8 KB sorted q

    const float* qsrt = g_qsrt + b * DD;
#pragma unroll
    for (int t = tid; t < DD / 4; t += 256)
        reinterpret_cast<float4*>(qs)[t] = reinterpret_cast<const float4*>(qsrt)[t];
    __syncthreads();

    const float qmax = g_qmax[b];
    const float qmin = g_qmin[b];

    const int w    = bx * 8 + (tid >> 5);
    const int slot = slot_map(w, tid & 31);

    const float k2 = g_k2s[b * DD + slot];
    const float vv = g_vs[b * DD + slot];

    int start, end;
    if (k2 >= 0.f) {
        // need q >= qmax - TCUT/k2  (k2==0 -> qlo=-inf -> full range)
        const float qlo = qmax - TCUT / k2;
        int lo = 0, hi = DD;
        while (lo < hi) { int mid = (lo + hi) >> 1; if (qs[mid] < qlo) lo = mid + 1; else hi = mid; }
        start = lo; end = DD;
    } else {
        // need q <= qmin - TCUT/k2
        const float qhi = qmin - TCUT / k2;
        int lo = 0, hi = DD;
        while (lo < hi) { int mid = (lo + hi) >> 1; if (qs[mid] <= qhi) lo = mid + 1; else hi = mid; }
        start = 0; end = lo;
    }

    const float qsel = (k2 >= 0.f) ? qmax : qmin;
    const float nm   = -k2 * qsel;

    float s0 = 0.f, s1 = 0.f, s2 = 0.f, s3 = 0.f;
    int idx = start;
    for (; idx + 4 <= end; idx += 4) {
        s0 += ex2f(fmaf(k2, qs[idx + 0], nm));
        s1 += ex2f(fmaf(k2, qs[idx + 1], nm));
        s2 += ex2f(fmaf(k2, qs[idx + 2], nm));
        s3 += ex2f(fmaf(k2, qs[idx + 3], nm));
    }
    for (; idx < end; idx++)
        s0 += ex2f(fmaf(k2, qs[idx], nm));

    const float S = (s0 + s1) + (s2 + s3);
    g_cp[b * DD + slot] = vv / S;
}

// ---------------------------------------------------------------------------
// Kernel C: pass 2. grid (8, 32), 256 threads. Thread owns one q-sorted
// position; sums c*exp over prefixes of the neg and pos k2 groups.
// ---------------------------------------------------------------------------
__global__ void __launch_bounds__(256) attn_pass2(float* __restrict__ out)
{
    const int b   = blockIdx.y;
    const int bx  = blockIdx.x;
    const int tid = threadIdx.x;

    __shared__ float k2s[DD];          // 8 KB
    __shared__ float cs[DD];           // 8 KB

    const float* k2row = g_k2s + b * DD;
    const float* crow  = g_cp + b * DD;
#pragma unroll
    for (int t = tid; t < DD / 4; t += 256) {
        reinterpret_cast<float4*>(k2s)[t] = reinterpret_cast<const float4*>(k2row)[t];
        reinterpret_cast<float4*>(cs)[t]  = reinterpret_cast<const float4*>(crow)[t];
    }
    __syncthreads();

    const float qmax = g_qmax[b];
    const float qmin = g_qmin[b];
    const int   nneg = g_nneg[b];

    const int w    = bx * 8 + (tid >> 5);
    const int qpos = slot_map(w, tid & 31);

    const float qi = g_qsrt[b * DD + qpos];
    const int   i  = g_qidx[b * DD + qpos];

    const float da = qmax - qi;        // >= 0
    const float db = qi - qmin;        // >= 0

    // negatives: slots [0, nneg), |k2| ascending (k2 descending).
    // include while k2 >= -TCUT/db  (db==0 -> -inf -> all)
    const float thrn = -TCUT / db;
    int lo = 0, hi = nneg;
    while (lo < hi) { int mid = (lo + hi) >> 1; if (k2s[mid] >= thrn) lo = mid + 1; else hi = mid; }
    const int ubn = lo;

    // positives: slots [nneg, DD), k2 ascending.
    // include while k2 <= TCUT/da  (da==0 -> +inf -> all)
    const float thrp = TCUT / da;
    lo = nneg; hi = DD;
    while (lo < hi) { int mid = (lo + hi) >> 1; if (k2s[mid] <= thrp) lo = mid + 1; else hi = mid; }
    const int ubp = lo;

    float s0 = 0.f, s1 = 0.f, s2 = 0.f, s3 = 0.f;

    // negative group: arg = k2 * (qi - qmin) = k2 * db  (<= 0)
    int idx = 0;
    for (; idx + 4 <= ubn; idx += 4) {
        s0 = fmaf(cs[idx + 0], ex2f(k2s[idx + 0] * db), s0);
        s1 = fmaf(cs[idx + 1], ex2f(k2s[idx + 1] * db), s1);
        s2 = fmaf(cs[idx + 2], ex2f(k2s[idx + 2] * db), s2);
        s3 = fmaf(cs[idx + 3], ex2f(k2s[idx + 3] * db), s3);
    }
    for (; idx < ubn; idx++)
        s0 = fmaf(cs[idx], ex2f(k2s[idx] * db), s0);

    // positive group: arg = k2 * (qi - qmax) = -k2 * da  (<= 0)
    const float mda = qi - qmax;       // = -da
    idx = nneg;
    for (; idx + 4 <= ubp; idx += 4) {
        s0 = fmaf(cs[idx + 0], ex2f(k2s[idx + 0] * mda), s0);
        s1 = fmaf(cs[idx + 1], ex2f(k2s[idx + 1] * mda), s1);
        s2 = fmaf(cs[idx + 2], ex2f(k2s[idx + 2] * mda), s2);
        s3 = fmaf(cs[idx + 3], ex2f(k2s[idx + 3] * mda), s3);
    }
    for (; idx < ubp; idx++)
        s0 = fmaf(cs[idx], ex2f(k2s[idx] * mda), s0);

    out[b * DD + i] = (s0 + s1) + (s2 + s3);
}

// ---------------------------------------------------------------------------

extern "C" void kernel_launch(void* const* d_in, const int* in_sizes, int n_in,
                              void* d_out, int out_size)
{
    const float* x  = (const float*)d_in[0];
    const float* Wq = (const float*)d_in[1];
    const float* bq = (const float*)d_in[2];
    const float* Wk = (const float*)d_in[3];
    const float* bk = (const float*)d_in[4];
    const float* Wv = (const float*)d_in[5];
    const float* bv = (const float*)d_in[6];
    float* out = (float*)d_out;

    qkv_gemm_part<<<384, 128>>>(x, Wq, Wk, Wv);
    qkv_combine<<<96, 512>>>(bq, bk, bv);
    prep<<<32, 1024>>>();
    attn_pass1<<<dim3(8, 32), 256>>>();
    attn_pass2<<<dim3(8, 32), 256>>>(out);
}

// round 16
// speedup vs baseline: 1.3824x; 1.3824x over previous
#include <cuda_runtime.h>
#include <cuda_bf16.h>

// SelfAttention: B=32, D=2048
// q = x@Wq^T+bq ; k,v similarly
// scores[b,i,j] = q_i*k_j ; softmax over i ; out_i = sum_j w_ij * v_j
//
// Rank-1 truncated attention with bucket ordering (no sort):
//   arg_ij = k2_j*(q_i - qsel_j) <= 0; terms with arg < -TCUT dropped.
//   prep:  stable 32-bucket counting-bucketize of q (payload idx) and of
//          k2 (payload v). Deterministic (no atomics).
//   pass1: thread owns k2-slot; included i's = bucket-aligned contiguous
//          range of bucketized q (O(1) arithmetic); c = v/S.
//   pass2: thread owns q-position; included j's = bucket-aligned range
//          [blo,bhi) of bucketized k2 containing 0.
// GEMM: fp32 via packed fma.rn.f32x2 (FFMA2, 2 MAC/slot), 144 CTAs = 1 wave.
// R14 fix: ws smem third dim 132 -> 260 (256-wide n tile + pad); OOB stomp
// was the illegal-memory-access root cause.

#define BB 32
#define DD 2048
#define LOG2E 1.4426950408889634f
#define TCUT 28.0f
#define NB 32
#define KSPLIT 6

typedef unsigned long long ull;

__device__ float g_q[BB * DD];
__device__ float g_k[BB * DD];
__device__ float g_v[BB * DD];
__device__ float g_part[KSPLIT][3 * BB * DD];

__device__ float g_qmaxA[BB], g_qminA[BB], g_qinvA[BB];
__device__ float g_k2minA[BB], g_kinvA[BB];
__device__ float g_qsrt[BB * DD];
__device__ int   g_qidx[BB * DD];
__device__ float g_k2s[BB * DD];
__device__ float g_vs[BB * DD];
__device__ float g_cp[BB * DD];
__device__ int   g_qbs[BB * (NB + 1)];
__device__ int   g_kbs[BB * (NB + 1)];

__constant__ int c_k0[KSPLIT]   = {0, 352, 704, 1040, 1376, 1712};
__constant__ int c_klen[KSPLIT] = {352, 352, 336, 336, 336, 336};

__device__ __forceinline__ float ex2f(float x) {
    float r;
    asm("ex2.approx.ftz.f32 %0, %1;" : "=f"(r) : "f"(x));
    return r;
}
__device__ __forceinline__ ull fma2(ull a, ull b, ull c) {
    ull d;
    asm("fma.rn.f32x2 %0, %1, %2, %3;" : "=l"(d) : "l"(a), "l"(b), "l"(c));
    return d;
}
__device__ __forceinline__ ull pack2f(float lo, float hi) {
    ull r;
    asm("mov.b64 %0, {%1, %2};" : "=l"(r) : "f"(lo), "f"(hi));
    return r;
}

// ---------------------------------------------------------------------------
// Kernel A: q/k/v GEMM partials via FFMA2.
// grid = 144 (KSPLIT=6 x 3 mats x 8 n-tiles), 128 threads.
// CTA tile 32m x 256n x klen; stage 16 kk, double-buffered.
// Thread tile 8m x 8n (two n-quads 32 apart -> conflict-free LDS.128).
// ---------------------------------------------------------------------------
__global__ void __launch_bounds__(128, 1) qkv_gemm_part(
    const float* __restrict__ x,
    const float* __restrict__ Wq,
    const float* __restrict__ Wk,
    const float* __restrict__ Wv)
{
    const int bx  = blockIdx.x;
    const int ks  = bx / 24;
    const int r   = bx % 24;
    const int mat = r >> 3;
    const int n0  = (r & 7) * 256;
    const int k0  = c_k0[ks];
    const int nst = c_klen[ks] >> 4;

    const float* W = (mat == 0) ? Wq : (mat == 1) ? Wk : Wv;

    __shared__ __align__(16) float xs[2][16][36];    // [buf][kk][m]
    __shared__ __align__(16) float ws[2][16][260];   // [buf][kk][n]  (256 + pad)

    const int tid  = threadIdx.x;
    const int lane = tid & 31;
    const int wid  = tid >> 5;
    const int tn   = lane & 7;
    const int tm   = lane >> 3;
    const int wcol = wid * 64 + tn * 4;              // n-quad A; quad B = +32

    const int lm = tid >> 2;                         // loader row 0..31
    const int lk = (tid & 3) * 4;                    // loader kq

    ull acc[8][4];
#pragma unroll
    for (int a = 0; a < 8; a++)
#pragma unroll
        for (int c = 0; c < 4; c++) acc[a][c] = 0ULL;

    float4 xr, wr[8];

    // prologue: stage 0
    xr = *reinterpret_cast<const float4*>(&x[lm * DD + k0 + lk]);
#pragma unroll
    for (int u = 0; u < 8; u++)
        wr[u] = *reinterpret_cast<const float4*>(&W[(n0 + u * 32 + lm) * DD + k0 + lk]);
    xs[0][lk + 0][lm] = xr.x;
    xs[0][lk + 1][lm] = xr.y;
    xs[0][lk + 2][lm] = xr.z;
    xs[0][lk + 3][lm] = xr.w;
#pragma unroll
    for (int u = 0; u < 8; u++) {
        const int n = u * 32 + lm;
        ws[0][lk + 0][n] = wr[u].x;
        ws[0][lk + 1][n] = wr[u].y;
        ws[0][lk + 2][n] = wr[u].z;
        ws[0][lk + 3][n] = wr[u].w;
    }

    for (int kt = 0; kt < nst; kt++) {
        const int p = kt & 1;
        __syncthreads();

        if (kt < nst - 1) {
            const int kb = k0 + (kt + 1) * 16;
            xr = *reinterpret_cast<const float4*>(&x[lm * DD + kb + lk]);
#pragma unroll
            for (int u = 0; u < 8; u++)
                wr[u] = *reinterpret_cast<const float4*>(&W[(n0 + u * 32 + lm) * DD + kb + lk]);
        }

#pragma unroll
        for (int kk = 0; kk < 16; kk++) {
            const float4 xa = *reinterpret_cast<const float4*>(&xs[p][kk][tm * 8]);
            const float4 xb = *reinterpret_cast<const float4*>(&xs[p][kk][tm * 8 + 4]);
            const ulonglong2 wa = *reinterpret_cast<const ulonglong2*>(&ws[p][kk][wcol]);
            const ulonglong2 wb = *reinterpret_cast<const ulonglong2*>(&ws[p][kk][wcol + 32]);
            float xm[8];
            xm[0] = xa.x; xm[1] = xa.y; xm[2] = xa.z; xm[3] = xa.w;
            xm[4] = xb.x; xm[5] = xb.y; xm[6] = xb.z; xm[7] = xb.w;
#pragma unroll
            for (int a = 0; a < 8; a++) {
                const ull xd = pack2f(xm[a], xm[a]);
                acc[a][0] = fma2(xd, wa.x, acc[a][0]);
                acc[a][1] = fma2(xd, wa.y, acc[a][1]);
                acc[a][2] = fma2(xd, wb.x, acc[a][2]);
                acc[a][3] = fma2(xd, wb.y, acc[a][3]);
            }
        }

        if (kt < nst - 1) {
            const int np = p ^ 1;
            xs[np][lk + 0][lm] = xr.x;
            xs[np][lk + 1][lm] = xr.y;
            xs[np][lk + 2][lm] = xr.z;
            xs[np][lk + 3][lm] = xr.w;
#pragma unroll
            for (int u = 0; u < 8; u++) {
                const int n = u * 32 + lm;
                ws[np][lk + 0][n] = wr[u].x;
                ws[np][lk + 1][n] = wr[u].y;
                ws[np][lk + 2][n] = wr[u].z;
                ws[np][lk + 3][n] = wr[u].w;
            }
        }
    }

    // epilogue: store partials
    float* dst = g_part[ks];
#pragma unroll
    for (int a = 0; a < 8; a++) {
        const int m = tm * 8 + a;
        float* rowp = &dst[(mat * BB + m) * DD + n0];
        ulonglong2 va; va.x = acc[a][0]; va.y = acc[a][1];
        ulonglong2 vb; vb.x = acc[a][2]; vb.y = acc[a][3];
        *reinterpret_cast<ulonglong2*>(&rowp[wcol])      = va;
        *reinterpret_cast<ulonglong2*>(&rowp[wcol + 32]) = vb;
    }
}

// ---------------------------------------------------------------------------
// Kernel A2: combine 6 k-split partials + bias -> g_q/g_k/g_v.
// ---------------------------------------------------------------------------
__global__ void __launch_bounds__(512) qkv_combine(
    const float* __restrict__ bq,
    const float* __restrict__ bk,
    const float* __restrict__ bv)
{
    const int idx4 = blockIdx.x * 512 + threadIdx.x;   // 0..49151
    float4 o = reinterpret_cast<const float4*>(g_part[0])[idx4];
#pragma unroll
    for (int s = 1; s < KSPLIT; s++) {
        const float4 p = reinterpret_cast<const float4*>(g_part[s])[idx4];
        o.x += p.x; o.y += p.y; o.z += p.z; o.w += p.w;
    }

    const int mat  = idx4 / (BB * DD / 4);
    const int rem  = idx4 % (BB * DD / 4);
    const int col4 = idx4 % (DD / 4);

    const float* bias = (mat == 0) ? bq : (mat == 1) ? bk : bv;
    const float4 b4 = reinterpret_cast<const float4*>(bias)[col4];
    o.x += b4.x; o.y += b4.y; o.z += b4.z; o.w += b4.w;

    float* dst = (mat == 0) ? g_q : (mat == 1) ? g_k : g_v;
    reinterpret_cast<float4*>(dst)[rem] = o;
}

// ---------------------------------------------------------------------------
// Kernel P: prep. grid = 32 (one CTA per batch), 256 threads.
// Stable counting-bucketize (NB buckets) of q (payload idx) and k2 (payload v).
// Deterministic: per-thread smem histograms + serial column scan, no atomics.
// ---------------------------------------------------------------------------
__global__ void __launch_bounds__(256) prep()
{
    const int b   = blockIdx.x;
    const int tid = threadIdx.x;

    __shared__ unsigned short cnt[256][NB + 1];
    __shared__ float rA[8], rB[8], rC[8], rD[8];
    __shared__ float s_qmax, s_qmin, s_kmax, s_kmin;
    __shared__ int   bstart[NB + 1];
    __shared__ int   tot[NB];

    const int base = tid * 8;
    float qv[8], kv[8], vv[8];
    {
        const float4 a0 = *reinterpret_cast<const float4*>(&g_q[b * DD + base]);
        const float4 a1 = *reinterpret_cast<const float4*>(&g_q[b * DD + base + 4]);
        qv[0] = a0.x; qv[1] = a0.y; qv[2] = a0.z; qv[3] = a0.w;
        qv[4] = a1.x; qv[5] = a1.y; qv[6] = a1.z; qv[7] = a1.w;
        const float4 c0 = *reinterpret_cast<const float4*>(&g_k[b * DD + base]);
        const float4 c1 = *reinterpret_cast<const float4*>(&g_k[b * DD + base + 4]);
        kv[0] = c0.x; kv[1] = c0.y; kv[2] = c0.z; kv[3] = c0.w;
        kv[4] = c1.x; kv[5] = c1.y; kv[6] = c1.z; kv[7] = c1.w;
        const float4 v0 = *reinterpret_cast<const float4*>(&g_v[b * DD + base]);
        const float4 v1 = *reinterpret_cast<const float4*>(&g_v[b * DD + base + 4]);
        vv[0] = v0.x; vv[1] = v0.y; vv[2] = v0.z; vv[3] = v0.w;
        vv[4] = v1.x; vv[5] = v1.y; vv[6] = v1.z; vv[7] = v1.w;
    }
#pragma unroll
    for (int u = 0; u < 8; u++) kv[u] *= LOG2E;

    // ---- reduce qmax/qmin/k2max/k2min ----
    float qmx = qv[0], qmn = qv[0], kmx = kv[0], kmn = kv[0];
#pragma unroll
    for (int u = 1; u < 8; u++) {
        qmx = fmaxf(qmx, qv[u]); qmn = fminf(qmn, qv[u]);
        kmx = fmaxf(kmx, kv[u]); kmn = fminf(kmn, kv[u]);
    }
#pragma unroll
    for (int o = 16; o; o >>= 1) {
        qmx = fmaxf(qmx, __shfl_xor_sync(0xffffffffu, qmx, o));
        qmn = fminf(qmn, __shfl_xor_sync(0xffffffffu, qmn, o));
        kmx = fmaxf(kmx, __shfl_xor_sync(0xffffffffu, kmx, o));
        kmn = fminf(kmn, __shfl_xor_sync(0xffffffffu, kmn, o));
    }
    if ((tid & 31) == 0) { rA[tid >> 5] = qmx; rB[tid >> 5] = qmn; rC[tid >> 5] = kmx; rD[tid >> 5] = kmn; }
    __syncthreads();
    if (tid < 8) {
        qmx = rA[tid]; qmn = rB[tid]; kmx = rC[tid]; kmn = rD[tid];
#pragma unroll
        for (int o = 4; o; o >>= 1) {
            qmx = fmaxf(qmx, __shfl_xor_sync(0xffu, qmx, o));
            qmn = fminf(qmn, __shfl_xor_sync(0xffu, qmn, o));
            kmx = fmaxf(kmx, __shfl_xor_sync(0xffu, kmx, o));
            kmn = fminf(kmn, __shfl_xor_sync(0xffu, kmn, o));
        }
        if (tid == 0) { s_qmax = qmx; s_qmin = qmn; s_kmax = kmx; s_kmin = kmn; }
    }
    __syncthreads();

    const float qmax = s_qmax, qmin = s_qmin;
    const float qinv = (float)NB / fmaxf(qmax - qmin, 1e-30f);
    const float kmin2 = s_kmin;
    const float kinv = (float)NB / fmaxf(s_kmax - kmin2, 1e-30f);

    // ======== bucketize q ========
#pragma unroll
    for (int j = 0; j < NB; j++) cnt[tid][j] = 0;
    __syncthreads();
#pragma unroll
    for (int u = 0; u < 8; u++) {
        const int bu = min(NB - 1, (int)((qv[u] - qmin) * qinv));
        cnt[tid][bu]++;
    }
    __syncthreads();
    if (tid < NB) {
        int off = 0;
        for (int t = 0; t < 256; t++) {
            const int c2 = cnt[t][tid];
            cnt[t][tid] = (unsigned short)off;
            off += c2;
        }
        tot[tid] = off;
    }
    __syncthreads();
    if (tid < 32) {
        const int v = tot[tid];
        int s = v;
#pragma unroll
        for (int o = 1; o < 32; o <<= 1) {
            const int n2 = __shfl_up_sync(0xffffffffu, s, o);
            if (tid >= o) s += n2;
        }
        bstart[tid] = s - v;
        if (tid == 31) bstart[32] = s;
    }
    __syncthreads();
#pragma unroll
    for (int u = 0; u < 8; u++) {
        const int bu = min(NB - 1, (int)((qv[u] - qmin) * qinv));
        const int pos = bstart[bu] + (int)cnt[tid][bu];
        cnt[tid][bu]++;
        g_qsrt[b * DD + pos] = qv[u];
        g_qidx[b * DD + pos] = base + u;
    }
    if (tid < NB + 1) g_qbs[b * (NB + 1) + tid] = bstart[tid];
    if (tid == 0) {
        g_qmaxA[b] = qmax; g_qminA[b] = qmin; g_qinvA[b] = qinv;
        g_k2minA[b] = kmin2; g_kinvA[b] = kinv;
    }
    __syncthreads();

    // ======== bucketize k2 ========
#pragma unroll
    for (int j = 0; j < NB; j++) cnt[tid][j] = 0;
    __syncthreads();
#pragma unroll
    for (int u = 0; u < 8; u++) {
        const int bu = min(NB - 1, (int)((kv[u] - kmin2) * kinv));
        cnt[tid][bu]++;
    }
    __syncthreads();
    if (tid < NB) {
        int off = 0;
        for (int t = 0; t < 256; t++) {
            const int c2 = cnt[t][tid];
            cnt[t][tid] = (unsigned short)off;
            off += c2;
        }
        tot[tid] = off;
    }
    __syncthreads();
    if (tid < 32) {
        const int v = tot[tid];
        int s = v;
#pragma unroll
        for (int o = 1; o < 32; o <<= 1) {
            const int n2 = __shfl_up_sync(0xffffffffu, s, o);
            if (tid >= o) s += n2;
        }
        bstart[tid] = s - v;
        if (tid == 31) bstart[32] = s;
    }
    __syncthreads();
#pragma unroll
    for (int u = 0; u < 8; u++) {
        const int bu = min(NB - 1, (int)((kv[u] - kmin2) * kinv));
        const int pos = bstart[bu] + (int)cnt[tid][bu];
        cnt[tid][bu]++;
        g_k2s[b * DD + pos] = kv[u];
        g_vs[b * DD + pos]  = vv[u];
    }
    if (tid < NB + 1) g_kbs[b * (NB + 1) + tid] = bstart[tid];
}

// ---------------------------------------------------------------------------
// Kernel B: pass 1. grid (8, 32), 256 threads. Thread owns one k2-slot;
// sums exp over bucket-aligned range of bucketized q. Balanced: warp g takes
// slots [g*32, +32) with g = wid*8 + bx (every CTA gets all work levels).
// ---------------------------------------------------------------------------
__global__ void __launch_bounds__(256) attn_pass1()
{
    const int b   = blockIdx.y;
    const int bx  = blockIdx.x;
    const int tid = threadIdx.x;

    __shared__ float qs[DD];
    __shared__ int   qbs[NB + 1];

    const float* qsrt = g_qsrt + b * DD;
#pragma unroll
    for (int t = tid; t < DD / 4; t += 256)
        reinterpret_cast<float4*>(qs)[t] = reinterpret_cast<const float4*>(qsrt)[t];
    if (tid < NB + 1) qbs[tid] = g_qbs[b * (NB + 1) + tid];
    __syncthreads();

    const float qmax = g_qmaxA[b];
    const float qmin = g_qminA[b];
    const float qinv = g_qinvA[b];

    const int g    = (tid >> 5) * 8 + bx;
    const int slot = g * 32 + (tid & 31);

    const float k2 = g_k2s[b * DD + slot];
    const float vv = g_vs[b * DD + slot];

    int start, end;
    float nm;
    if (k2 >= 0.f) {
        const float qlo = qmax - TCUT / k2;
        const int bb = (int)fmaxf(0.f, fminf((float)(NB - 1), floorf((qlo - qmin) * qinv)));
        start = qbs[bb]; end = DD;
        nm = -k2 * qmax;
    } else {
        const float qhi = qmin - TCUT / k2;
        const int bb = (int)fmaxf(1.f, fminf((float)NB, floorf((qhi - qmin) * qinv) + 1.f));
        start = 0; end = qbs[bb];
        nm = -k2 * qmin;
    }

    float s0 = 0.f, s1 = 0.f, s2 = 0.f, s3 = 0.f;
    int idx = start;
    for (; idx + 4 <= end; idx += 4) {
        s0 += ex2f(fmaf(k2, qs[idx + 0], nm));
        s1 += ex2f(fmaf(k2, qs[idx + 1], nm));
        s2 += ex2f(fmaf(k2, qs[idx + 2], nm));
        s3 += ex2f(fmaf(k2, qs[idx + 3], nm));
    }
    for (; idx < end; idx++)
        s0 += ex2f(fmaf(k2, qs[idx], nm));

    const float S = (s0 + s1) + (s2 + s3);
    g_cp[b * DD + slot] = vv / S;
}

// ---------------------------------------------------------------------------
// Kernel C: pass 2. grid (8, 32), 256 threads. Thread owns one q-position;
// sums c*exp over bucket-aligned range [blo,bhi) of bucketized k2.
// ---------------------------------------------------------------------------
__global__ void __launch_bounds__(256) attn_pass2(float* __restrict__ out)
{
    const int b   = blockIdx.y;
    const int bx  = blockIdx.x;
    const int tid = threadIdx.x;

    __shared__ float k2s[DD];
    __shared__ float nms[DD];
    __shared__ float cs[DD];
    __shared__ int   kbs[NB + 1];

    const float qmax = g_qmaxA[b];
    const float qmin = g_qminA[b];

    const float* k2row = g_k2s + b * DD;
    const float* crow  = g_cp + b * DD;
#pragma unroll
    for (int t = tid; t < DD / 4; t += 256) {
        const float4 kk4 = reinterpret_cast<const float4*>(k2row)[t];
        const float4 cc4 = reinterpret_cast<const float4*>(crow)[t];
        float4 nm4;
        nm4.x = -kk4.x * (kk4.x >= 0.f ? qmax : qmin);
        nm4.y = -kk4.y * (kk4.y >= 0.f ? qmax : qmin);
        nm4.z = -kk4.z * (kk4.z >= 0.f ? qmax : qmin);
        nm4.w = -kk4.w * (kk4.w >= 0.f ? qmax : qmin);
        reinterpret_cast<float4*>(k2s)[t] = kk4;
        reinterpret_cast<float4*>(nms)[t] = nm4;
        reinterpret_cast<float4*>(cs)[t]  = cc4;
    }
    if (tid < NB + 1) kbs[tid] = g_kbs[b * (NB + 1) + tid];
    __syncthreads();

    const float k2min = g_k2minA[b];
    const float kinv  = g_kinvA[b];

    const int g = (tid >> 5) * 8 + bx;
    const int p = g * 32 + (tid & 31);

    const float qi = g_qsrt[b * DD + p];
    const int   i  = g_qidx[b * DD + p];

    const float da = qmax - qi;
    const float db = qi - qmin;
    const float thrn = -TCUT / db;   // db=0 -> -inf -> blo=0
    const float thrp =  TCUT / da;   // da=0 -> +inf -> bhi=NB

    const int blo = (int)fmaxf(0.f, fminf((float)NB, floorf((thrn - k2min) * kinv)));
    const int bhi = (int)fmaxf(0.f, fminf((float)NB, floorf((thrp - k2min) * kinv) + 1.f));
    const int start = kbs[blo];
    const int end   = kbs[bhi];

    float s0 = 0.f, s1 = 0.f, s2 = 0.f, s3 = 0.f;
    int idx = start;
    for (; idx + 4 <= end; idx += 4) {
        s0 = fmaf(cs[idx + 0], ex2f(fmaf(k2s[idx + 0], qi, nms[idx + 0])), s0);
        s1 = fmaf(cs[idx + 1], ex2f(fmaf(k2s[idx + 1], qi, nms[idx + 1])), s1);
        s2 = fmaf(cs[idx + 2], ex2f(fmaf(k2s[idx + 2], qi, nms[idx + 2])), s2);
        s3 = fmaf(cs[idx + 3], ex2f(fmaf(k2s[idx + 3], qi, nms[idx + 3])), s3);
    }
    for (; idx < end; idx++)
        s0 = fmaf(cs[idx], ex2f(fmaf(k2s[idx], qi, nms[idx])), s0);

    out[b * DD + i] = (s0 + s1) + (s2 + s3);
}

// ---------------------------------------------------------------------------

extern "C" void kernel_launch(void* const* d_in, const int* in_sizes, int n_in,
                              void* d_out, int out_size)
{
    const float* x  = (const float*)d_in[0];
    const float* Wq = (const float*)d_in[1];
    const float* bq = (const float*)d_in[2];
    const float* Wk = (const float*)d_in[3];
    const float* bk = (const float*)d_in[4];
    const float* Wv = (const float*)d_in[5];
    const float* bv = (const float*)d_in[6];
    float* out = (float*)d_out;

    qkv_gemm_part<<<144, 128>>>(x, Wq, Wk, Wv);
    qkv_combine<<<96, 512>>>(bq, bk, bv);
    prep<<<32, 256>>>();
    attn_pass1<<<dim3(8, 32), 256>>>();
    attn_pass2<<<dim3(8, 32), 256>>>(out);
}

// round 17
// speedup vs baseline: 1.5278x; 1.1052x over previous
#include <cuda_runtime.h>
#include <cuda_bf16.h>

// SelfAttention: B=32, D=2048
// q = x@Wq^T+bq ; k,v similarly
// scores[b,i,j] = q_i*k_j ; softmax over i ; out_i = sum_j w_ij * v_j
//
// Rank-1 truncated attention with bucket ordering (no sort):
//   arg_ij = k2_j*(q_i - qsel_j) <= 0; terms with arg < -TCUT dropped.
//   prep:  stable 32-bucket counting-bucketize of q (payload idx) and of
//          k2 (payload v). Deterministic (no atomics).
//   pass1: slot s (k2-ordered); included i's = bucket-aligned range of
//          bucketized q; 2 threads per slot (half-range each) -> c = v/S.
//   pass2: q-position; included j's = bucket-aligned range of bucketized
//          k2; 2 threads per position (half-range each).
// GEMM: fp32 via packed fma.rn.f32x2 (FFMA2), 144 CTAs = 1 wave.

#define BB 32
#define DD 2048
#define LOG2E 1.4426950408889634f
#define TCUT 24.0f
#define NB 32
#define KSPLIT 6

typedef unsigned long long ull;

__device__ float g_q[BB * DD];
__device__ float g_k[BB * DD];
__device__ float g_v[BB * DD];
__device__ float g_part[KSPLIT][3 * BB * DD];

__device__ float g_qmaxA[BB], g_qminA[BB], g_qinvA[BB];
__device__ float g_k2minA[BB], g_kinvA[BB];
__device__ float g_qsrt[BB * DD];
__device__ int   g_qidx[BB * DD];
__device__ float g_k2s[BB * DD];
__device__ float g_vs[BB * DD];
__device__ float g_cp[BB * DD];
__device__ int   g_qbs[BB * (NB + 1)];
__device__ int   g_kbs[BB * (NB + 1)];

__constant__ int c_k0[KSPLIT]   = {0, 352, 704, 1040, 1376, 1712};
__constant__ int c_klen[KSPLIT] = {352, 352, 336, 336, 336, 336};

__device__ __forceinline__ float ex2f(float x) {
    float r;
    asm("ex2.approx.ftz.f32 %0, %1;" : "=f"(r) : "f"(x));
    return r;
}
__device__ __forceinline__ ull fma2(ull a, ull b, ull c) {
    ull d;
    asm("fma.rn.f32x2 %0, %1, %2, %3;" : "=l"(d) : "l"(a), "l"(b), "l"(c));
    return d;
}
__device__ __forceinline__ ull pack2f(float lo, float hi) {
    ull r;
    asm("mov.b64 %0, {%1, %2};" : "=l"(r) : "f"(lo), "f"(hi));
    return r;
}

// ---------------------------------------------------------------------------
// Kernel A: q/k/v GEMM partials via FFMA2. (unchanged from R16)
// ---------------------------------------------------------------------------
__global__ void __launch_bounds__(128, 1) qkv_gemm_part(
    const float* __restrict__ x,
    const float* __restrict__ Wq,
    const float* __restrict__ Wk,
    const float* __restrict__ Wv)
{
    const int bx  = blockIdx.x;
    const int ks  = bx / 24;
    const int r   = bx % 24;
    const int mat = r >> 3;
    const int n0  = (r & 7) * 256;
    const int k0  = c_k0[ks];
    const int nst = c_klen[ks] >> 4;

    const float* W = (mat == 0) ? Wq : (mat == 1) ? Wk : Wv;

    __shared__ __align__(16) float xs[2][16][36];    // [buf][kk][m]
    __shared__ __align__(16) float ws[2][16][260];   // [buf][kk][n]  (256 + pad)

    const int tid  = threadIdx.x;
    const int lane = tid & 31;
    const int wid  = tid >> 5;
    const int tn   = lane & 7;
    const int tm   = lane >> 3;
    const int wcol = wid * 64 + tn * 4;

    const int lm = tid >> 2;
    const int lk = (tid & 3) * 4;

    ull acc[8][4];
#pragma unroll
    for (int a = 0; a < 8; a++)
#pragma unroll
        for (int c = 0; c < 4; c++) acc[a][c] = 0ULL;

    float4 xr, wr[8];

    xr = *reinterpret_cast<const float4*>(&x[lm * DD + k0 + lk]);
#pragma unroll
    for (int u = 0; u < 8; u++)
        wr[u] = *reinterpret_cast<const float4*>(&W[(n0 + u * 32 + lm) * DD + k0 + lk]);
    xs[0][lk + 0][lm] = xr.x;
    xs[0][lk + 1][lm] = xr.y;
    xs[0][lk + 2][lm] = xr.z;
    xs[0][lk + 3][lm] = xr.w;
#pragma unroll
    for (int u = 0; u < 8; u++) {
        const int n = u * 32 + lm;
        ws[0][lk + 0][n] = wr[u].x;
        ws[0][lk + 1][n] = wr[u].y;
        ws[0][lk + 2][n] = wr[u].z;
        ws[0][lk + 3][n] = wr[u].w;
    }

    for (int kt = 0; kt < nst; kt++) {
        const int p = kt & 1;
        __syncthreads();

        if (kt < nst - 1) {
            const int kb = k0 + (kt + 1) * 16;
            xr = *reinterpret_cast<const float4*>(&x[lm * DD + kb + lk]);
#pragma unroll
            for (int u = 0; u < 8; u++)
                wr[u] = *reinterpret_cast<const float4*>(&W[(n0 + u * 32 + lm) * DD + kb + lk]);
        }

#pragma unroll
        for (int kk = 0; kk < 16; kk++) {
            const float4 xa = *reinterpret_cast<const float4*>(&xs[p][kk][tm * 8]);
            const float4 xb = *reinterpret_cast<const float4*>(&xs[p][kk][tm * 8 + 4]);
            const ulonglong2 wa = *reinterpret_cast<const ulonglong2*>(&ws[p][kk][wcol]);
            const ulonglong2 wb = *reinterpret_cast<const ulonglong2*>(&ws[p][kk][wcol + 32]);
            float xm[8];
            xm[0] = xa.x; xm[1] = xa.y; xm[2] = xa.z; xm[3] = xa.w;
            xm[4] = xb.x; xm[5] = xb.y; xm[6] = xb.z; xm[7] = xb.w;
#pragma unroll
            for (int a = 0; a < 8; a++) {
                const ull xd = pack2f(xm[a], xm[a]);
                acc[a][0] = fma2(xd, wa.x, acc[a][0]);
                acc[a][1] = fma2(xd, wa.y, acc[a][1]);
                acc[a][2] = fma2(xd, wb.x, acc[a][2]);
                acc[a][3] = fma2(xd, wb.y, acc[a][3]);
            }
        }

        if (kt < nst - 1) {
            const int np = p ^ 1;
            xs[np][lk + 0][lm] = xr.x;
            xs[np][lk + 1][lm] = xr.y;
            xs[np][lk + 2][lm] = xr.z;
            xs[np][lk + 3][lm] = xr.w;
#pragma unroll
            for (int u = 0; u < 8; u++) {
                const int n = u * 32 + lm;
                ws[np][lk + 0][n] = wr[u].x;
                ws[np][lk + 1][n] = wr[u].y;
                ws[np][lk + 2][n] = wr[u].z;
                ws[np][lk + 3][n] = wr[u].w;
            }
        }
    }

    float* dst = g_part[ks];
#pragma unroll
    for (int a = 0; a < 8; a++) {
        const int m = tm * 8 + a;
        float* rowp = &dst[(mat * BB + m) * DD + n0];
        ulonglong2 va; va.x = acc[a][0]; va.y = acc[a][1];
        ulonglong2 vb; vb.x = acc[a][2]; vb.y = acc[a][3];
        *reinterpret_cast<ulonglong2*>(&rowp[wcol])      = va;
        *reinterpret_cast<ulonglong2*>(&rowp[wcol + 32]) = vb;
    }
}

// ---------------------------------------------------------------------------
// Kernel A2: combine 6 k-split partials + bias -> g_q/g_k/g_v. (unchanged)
// ---------------------------------------------------------------------------
__global__ void __launch_bounds__(512) qkv_combine(
    const float* __restrict__ bq,
    const float* __restrict__ bk,
    const float* __restrict__ bv)
{
    const int idx4 = blockIdx.x * 512 + threadIdx.x;
    float4 o = reinterpret_cast<const float4*>(g_part[0])[idx4];
#pragma unroll
    for (int s = 1; s < KSPLIT; s++) {
        const float4 p = reinterpret_cast<const float4*>(g_part[s])[idx4];
        o.x += p.x; o.y += p.y; o.z += p.z; o.w += p.w;
    }

    const int mat  = idx4 / (BB * DD / 4);
    const int rem  = idx4 % (BB * DD / 4);
    const int col4 = idx4 % (DD / 4);

    const float* bias = (mat == 0) ? bq : (mat == 1) ? bk : bv;
    const float4 b4 = reinterpret_cast<const float4*>(bias)[col4];
    o.x += b4.x; o.y += b4.y; o.z += b4.z; o.w += b4.w;

    float* dst = (mat == 0) ? g_q : (mat == 1) ? g_k : g_v;
    reinterpret_cast<float4*>(dst)[rem] = o;
}

// ---------------------------------------------------------------------------
// Kernel P: prep. (unchanged from R16)
// ---------------------------------------------------------------------------
__global__ void __launch_bounds__(256) prep()
{
    const int b   = blockIdx.x;
    const int tid = threadIdx.x;

    __shared__ unsigned short cnt[256][NB + 1];
    __shared__ float rA[8], rB[8], rC[8], rD[8];
    __shared__ float s_qmax, s_qmin, s_kmax, s_kmin;
    __shared__ int   bstart[NB + 1];
    __shared__ int   tot[NB];

    const int base = tid * 8;
    float qv[8], kv[8], vv[8];
    {
        const float4 a0 = *reinterpret_cast<const float4*>(&g_q[b * DD + base]);
        const float4 a1 = *reinterpret_cast<const float4*>(&g_q[b * DD + base + 4]);
        qv[0] = a0.x; qv[1] = a0.y; qv[2] = a0.z; qv[3] = a0.w;
        qv[4] = a1.x; qv[5] = a1.y; qv[6] = a1.z; qv[7] = a1.w;
        const float4 c0 = *reinterpret_cast<const float4*>(&g_k[b * DD + base]);
        const float4 c1 = *reinterpret_cast<const float4*>(&g_k[b * DD + base + 4]);
        kv[0] = c0.x; kv[1] = c0.y; kv[2] = c0.z; kv[3] = c0.w;
        kv[4] = c1.x; kv[5] = c1.y; kv[6] = c1.z; kv[7] = c1.w;
        const float4 v0 = *reinterpret_cast<const float4*>(&g_v[b * DD + base]);
        const float4 v1 = *reinterpret_cast<const float4*>(&g_v[b * DD + base + 4]);
        vv[0] = v0.x; vv[1] = v0.y; vv[2] = v0.z; vv[3] = v0.w;
        vv[4] = v1.x; vv[5] = v1.y; vv[6] = v1.z; vv[7] = v1.w;
    }
#pragma unroll
    for (int u = 0; u < 8; u++) kv[u] *= LOG2E;

    float qmx = qv[0], qmn = qv[0], kmx = kv[0], kmn = kv[0];
#pragma unroll
    for (int u = 1; u < 8; u++) {
        qmx = fmaxf(qmx, qv[u]); qmn = fminf(qmn, qv[u]);
        kmx = fmaxf(kmx, kv[u]); kmn = fminf(kmn, kv[u]);
    }
#pragma unroll
    for (int o = 16; o; o >>= 1) {
        qmx = fmaxf(qmx, __shfl_xor_sync(0xffffffffu, qmx, o));
        qmn = fminf(qmn, __shfl_xor_sync(0xffffffffu, qmn, o));
        kmx = fmaxf(kmx, __shfl_xor_sync(0xffffffffu, kmx, o));
        kmn = fminf(kmn, __shfl_xor_sync(0xffffffffu, kmn, o));
    }
    if ((tid & 31) == 0) { rA[tid >> 5] = qmx; rB[tid >> 5] = qmn; rC[tid >> 5] = kmx; rD[tid >> 5] = kmn; }
    __syncthreads();
    if (tid < 8) {
        qmx = rA[tid]; qmn = rB[tid]; kmx = rC[tid]; kmn = rD[tid];
#pragma unroll
        for (int o = 4; o; o >>= 1) {
            qmx = fmaxf(qmx, __shfl_xor_sync(0xffu, qmx, o));
            qmn = fminf(qmn, __shfl_xor_sync(0xffu, qmn, o));
            kmx = fmaxf(kmx, __shfl_xor_sync(0xffu, kmx, o));
            kmn = fminf(kmn, __shfl_xor_sync(0xffu, kmn, o));
        }
        if (tid == 0) { s_qmax = qmx; s_qmin = qmn; s_kmax = kmx; s_kmin = kmn; }
    }
    __syncthreads();

    const float qmax = s_qmax, qmin = s_qmin;
    const float qinv = (float)NB / fmaxf(qmax - qmin, 1e-30f);
    const float kmin2 = s_kmin;
    const float kinv = (float)NB / fmaxf(s_kmax - kmin2, 1e-30f);

    // ======== bucketize q ========
#pragma unroll
    for (int j = 0; j < NB; j++) cnt[tid][j] = 0;
    __syncthreads();
#pragma unroll
    for (int u = 0; u < 8; u++) {
        const int bu = min(NB - 1, (int)((qv[u] - qmin) * qinv));
        cnt[tid][bu]++;
    }
    __syncthreads();
    if (tid < NB) {
        int off = 0;
        for (int t = 0; t < 256; t++) {
            const int c2 = cnt[t][tid];
            cnt[t][tid] = (unsigned short)off;
            off += c2;
        }
        tot[tid] = off;
    }
    __syncthreads();
    if (tid < 32) {
        const int v = tot[tid];
        int s = v;
#pragma unroll
        for (int o = 1; o < 32; o <<= 1) {
            const int n2 = __shfl_up_sync(0xffffffffu, s, o);
            if (tid >= o) s += n2;
        }
        bstart[tid] = s - v;
        if (tid == 31) bstart[32] = s;
    }
    __syncthreads();
#pragma unroll
    for (int u = 0; u < 8; u++) {
        const int bu = min(NB - 1, (int)((qv[u] - qmin) * qinv));
        const int pos = bstart[bu] + (int)cnt[tid][bu];
        cnt[tid][bu]++;
        g_qsrt[b * DD + pos] = qv[u];
        g_qidx[b * DD + pos] = base + u;
    }
    if (tid < NB + 1) g_qbs[b * (NB + 1) + tid] = bstart[tid];
    if (tid == 0) {
        g_qmaxA[b] = qmax; g_qminA[b] = qmin; g_qinvA[b] = qinv;
        g_k2minA[b] = kmin2; g_kinvA[b] = kinv;
    }
    __syncthreads();

    // ======== bucketize k2 ========
#pragma unroll
    for (int j = 0; j < NB; j++) cnt[tid][j] = 0;
    __syncthreads();
#pragma unroll
    for (int u = 0; u < 8; u++) {
        const int bu = min(NB - 1, (int)((kv[u] - kmin2) * kinv));
        cnt[tid][bu]++;
    }
    __syncthreads();
    if (tid < NB) {
        int off = 0;
        for (int t = 0; t < 256; t++) {
            const int c2 = cnt[t][tid];
            cnt[t][tid] = (unsigned short)off;
            off += c2;
        }
        tot[tid] = off;
    }
    __syncthreads();
    if (tid < 32) {
        const int v = tot[tid];
        int s = v;
#pragma unroll
        for (int o = 1; o < 32; o <<= 1) {
            const int n2 = __shfl_up_sync(0xffffffffu, s, o);
            if (tid >= o) s += n2;
        }
        bstart[tid] = s - v;
        if (tid == 31) bstart[32] = s;
    }
    __syncthreads();
#pragma unroll
    for (int u = 0; u < 8; u++) {
        const int bu = min(NB - 1, (int)((kv[u] - kmin2) * kinv));
        const int pos = bstart[bu] + (int)cnt[tid][bu];
        cnt[tid][bu]++;
        g_k2s[b * DD + pos] = kv[u];
        g_vs[b * DD + pos]  = vv[u];
    }
    if (tid < NB + 1) g_kbs[b * (NB + 1) + tid] = bstart[tid];
}

// ---------------------------------------------------------------------------
// Kernel B: pass 1. grid (8, 32), 512 threads. TWO threads per k2-slot:
// tid&255 selects slot (balanced map), tid>>8 selects half of the i-range.
// ---------------------------------------------------------------------------
__global__ void __launch_bounds__(512) attn_pass1()
{
    const int b   = blockIdx.y;
    const int bx  = blockIdx.x;
    const int tid = threadIdx.x;

    __shared__ float qs[DD];
    __shared__ float Sh[512];
    __shared__ int   qbs[NB + 1];

    const float* qsrt = g_qsrt + b * DD;
#pragma unroll
    for (int t = tid; t < DD / 4; t += 512)
        reinterpret_cast<float4*>(qs)[t] = reinterpret_cast<const float4*>(qsrt)[t];
    if (tid < NB + 1) qbs[tid] = g_qbs[b * (NB + 1) + tid];
    __syncthreads();

    const float qmax = g_qmaxA[b];
    const float qmin = g_qminA[b];
    const float qinv = g_qinvA[b];

    const int sl   = tid & 255;
    const int h    = tid >> 8;
    const int g    = (sl >> 5) * 8 + bx;
    const int slot = g * 32 + (sl & 31);

    const float k2 = g_k2s[b * DD + slot];
    const float vv = g_vs[b * DD + slot];

    int start, end;
    float nm;
    if (k2 >= 0.f) {
        const float qlo = qmax - TCUT / k2;
        const int bb = (int)fmaxf(0.f, fminf((float)(NB - 1), floorf((qlo - qmin) * qinv)));
        start = qbs[bb]; end = DD;
        nm = -k2 * qmax;
    } else {
        const float qhi = qmin - TCUT / k2;
        const int bb = (int)fmaxf(1.f, fminf((float)NB, floorf((qhi - qmin) * qinv) + 1.f));
        start = 0; end = qbs[bb];
        nm = -k2 * qmin;
    }

    // split range across the two threads owning this slot
    const int mid = start + ((end - start) >> 1);
    const int s_  = h ? mid : start;
    const int e_  = h ? end : mid;

    float s0 = 0.f, s1 = 0.f, s2 = 0.f, s3 = 0.f;
    int idx = s_;
    for (; idx + 4 <= e_; idx += 4) {
        s0 += ex2f(fmaf(k2, qs[idx + 0], nm));
        s1 += ex2f(fmaf(k2, qs[idx + 1], nm));
        s2 += ex2f(fmaf(k2, qs[idx + 2], nm));
        s3 += ex2f(fmaf(k2, qs[idx + 3], nm));
    }
    for (; idx < e_; idx++)
        s0 += ex2f(fmaf(k2, qs[idx], nm));

    Sh[tid] = (s0 + s1) + (s2 + s3);
    __syncthreads();
    if (tid < 256) {
        const float S = Sh[tid] + Sh[tid + 256];
        g_cp[b * DD + slot] = vv / S;
    }
}

// ---------------------------------------------------------------------------
// Kernel C: pass 2. grid (8, 32), 512 threads. TWO threads per q-position:
// tid&255 selects position, tid>>8 selects half of the j-range.
// ---------------------------------------------------------------------------
__global__ void __launch_bounds__(512) attn_pass2(float* __restrict__ out)
{
    const int b   = blockIdx.y;
    const int bx  = blockIdx.x;
    const int tid = threadIdx.x;

    __shared__ float k2s[DD];
    __shared__ float nms[DD];
    __shared__ float cs[DD];
    __shared__ float Sh[512];
    __shared__ int   kbs[NB + 1];

    const float qmax = g_qmaxA[b];
    const float qmin = g_qminA[b];

    const float* k2row = g_k2s + b * DD;
    const float* crow  = g_cp + b * DD;
#pragma unroll
    for (int t = tid; t < DD / 4; t += 512) {
        const float4 kk4 = reinterpret_cast<const float4*>(k2row)[t];
        const float4 cc4 = reinterpret_cast<const float4*>(crow)[t];
        float4 nm4;
        nm4.x = -kk4.x * (kk4.x >= 0.f ? qmax : qmin);
        nm4.y = -kk4.y * (kk4.y >= 0.f ? qmax : qmin);
        nm4.z = -kk4.z * (kk4.z >= 0.f ? qmax : qmin);
        nm4.w = -kk4.w * (kk4.w >= 0.f ? qmax : qmin);
        reinterpret_cast<float4*>(k2s)[t] = kk4;
        reinterpret_cast<float4*>(nms)[t] = nm4;
        reinterpret_cast<float4*>(cs)[t]  = cc4;
    }
    if (tid < NB + 1) kbs[tid] = g_kbs[b * (NB + 1) + tid];
    __syncthreads();

    const float k2min = g_k2minA[b];
    const float kinv  = g_kinvA[b];

    const int sl = tid & 255;
    const int h  = tid >> 8;
    const int g  = (sl >> 5) * 8 + bx;
    const int p  = g * 32 + (sl & 31);

    const float qi = g_qsrt[b * DD + p];
    const int   i  = g_qidx[b * DD + p];

    const float da = qmax - qi;
    const float db = qi - qmin;
    const float thrn = -TCUT / db;   // db=0 -> -inf -> blo=0
    const float thrp =  TCUT / da;   // da=0 -> +inf -> bhi=NB

    const int blo = (int)fmaxf(0.f, fminf((float)NB, floorf((thrn - k2min) * kinv)));
    const int bhi = (int)fmaxf(0.f, fminf((float)NB, floorf((thrp - k2min) * kinv) + 1.f));
    const int start = kbs[blo];
    const int end   = kbs[bhi];

    const int mid = start + ((end - start) >> 1);
    const int s_  = h ? mid : start;
    const int e_  = h ? end : mid;

    float s0 = 0.f, s1 = 0.f, s2 = 0.f, s3 = 0.f;
    int idx = s_;
    for (; idx + 4 <= e_; idx += 4) {
        s0 = fmaf(cs[idx + 0], ex2f(fmaf(k2s[idx + 0], qi, nms[idx + 0])), s0);
        s1 = fmaf(cs[idx + 1], ex2f(fmaf(k2s[idx + 1], qi, nms[idx + 1])), s1);
        s2 = fmaf(cs[idx + 2], ex2f(fmaf(k2s[idx + 2], qi, nms[idx + 2])), s2);
        s3 = fmaf(cs[idx + 3], ex2f(fmaf(k2s[idx + 3], qi, nms[idx + 3])), s3);
    }
    for (; idx < e_; idx++)
        s0 = fmaf(cs[idx], ex2f(fmaf(k2s[idx], qi, nms[idx])), s0);

    Sh[tid] = (s0 + s1) + (s2 + s3);
    __syncthreads();
    if (tid < 256) {
        out[b * DD + i] = Sh[tid] + Sh[tid + 256];
    }
}

// ---------------------------------------------------------------------------

extern "C" void kernel_launch(void* const* d_in, const int* in_sizes, int n_in,
                              void* d_out, int out_size)
{
    const float* x  = (const float*)d_in[0];
    const float* Wq = (const float*)d_in[1];
    const float* bq = (const float*)d_in[2];
    const float* Wk = (const float*)d_in[3];
    const float* bk = (const float*)d_in[4];
    const float* Wv = (const float*)d_in[5];
    const float* bv = (const float*)d_in[6];
    float* out = (float*)d_out;

    qkv_gemm_part<<<144, 128>>>(x, Wq, Wk, Wv);
    qkv_combine<<<96, 512>>>(bq, bk, bv);
    prep<<<32, 256>>>();
    attn_pass1<<<dim3(8, 32), 512>>>();
    attn_pass2<<<dim3(8, 32), 512>>>(out);
}